// round 17
// baseline (speedup 1.0000x reference)
#include <cuda_runtime.h>
#include <cuda_fp16.h>
#include <cstdint>
#include <cmath>

#define T_SEQ 256
#define BATCH 64
#define EMB   512
#define HID   1024
#define GATES 4096   // 4*HID, gate order i,f,g,o
#define VOCAB 32000

#define NCTA     128
#define NTHREADS 256

// ---- persistent-kernel smem layout (R10, unchanged) ----
#define SW_STRIDE 516                    // uint32 words per W row (1032 halfs)
#define SA_STRIDE 132                    // uint32 words per A row per chunk
#define SA_BUF_W  (64 * SA_STRIDE)
#define GBUF_W    (64 * 33)
#define SMO_W     64
#define SMO_A     (SMO_W + 32 * SW_STRIDE * 4)
#define SMO_GBUF  (SMO_A + 3 * SA_BUF_W * 4)
#define SMEM_BYTES (SMO_GBUF + 2 * GBUF_W * 4)           // 184384

// ---- input_gemm tile constants (3-stage, dynamic smem) ----
#define IG_STRIDE 20                     // words per tile row (16 + 4 pad)
#define IG_TILE_W (128 * IG_STRIDE)      // 2560 words per tile buffer
#define IG_SMEM_BYTES (6 * IG_TILE_W * 4)   // 3 bufs x (A+B) = 61440 B

// ---------------- scratch (device globals) ---------------------------------
__device__ __align__(16) __half g_xgates[(size_t)T_SEQ * BATCH * GATES];  // fp16
__device__ __align__(16) __half g_h[2][BATCH * HID];     // double-buffered
__device__ __align__(16) float  g_c[BATCH * HID];
__device__ __align__(16) __half g_emb_h[(size_t)VOCAB * EMB];   // fp16 emb (32 MB)
__device__ __align__(16) __half g_wih_h[(size_t)GATES * EMB];   // fp16 W_ih (4 MB)
__device__ unsigned g_bar;               // monotonic grid barrier

// ---------------- helpers ---------------------------------------------------
// fp16 m16n8k16, fp32 accum
__device__ __forceinline__ void mma_f16(float* d, const uint32_t* a, uint32_t b0, uint32_t b1) {
    asm volatile(
        "mma.sync.aligned.m16n8k16.row.col.f32.f16.f16.f32 "
        "{%0,%1,%2,%3}, {%4,%5,%6,%7}, {%8,%9}, {%0,%1,%2,%3};\n"
        : "+f"(d[0]), "+f"(d[1]), "+f"(d[2]), "+f"(d[3])
        : "r"(a[0]), "r"(a[1]), "r"(a[2]), "r"(a[3]),
          "r"(b0), "r"(b1));
}

__device__ __forceinline__ void ldsm_x4(uint32_t& r0, uint32_t& r1, uint32_t& r2,
                                        uint32_t& r3, uint32_t addr) {
    asm volatile("ldmatrix.sync.aligned.m8n8.x4.shared.b16 {%0,%1,%2,%3}, [%4];"
                 : "=r"(r0), "=r"(r1), "=r"(r2), "=r"(r3) : "r"(addr));
}

__device__ __forceinline__ void cp_async16(uint32_t saddr, const void* gaddr) {
    asm volatile("cp.async.cg.shared.global [%0], [%1], 16;\n" :: "r"(saddr), "l"(gaddr));
}
__device__ __forceinline__ void cp_commit() { asm volatile("cp.async.commit_group;\n"); }
__device__ __forceinline__ void cp_wait0()  { asm volatile("cp.async.wait_group 0;\n"); }
__device__ __forceinline__ void cp_wait1()  { asm volatile("cp.async.wait_group 1;\n"); }

__device__ __forceinline__ uint32_t smem_u32(const void* p) {
    return (uint32_t)__cvta_generic_to_shared(p);
}

__device__ __forceinline__ uint32_t pack_h2(float x, float y) {
    __half2 hv = __floats2half2_rn(x, y);
    return *(uint32_t*)&hv;
}

// fast gate functions (MUFU-based; err ~1e-6, negligible vs fp16 quantization)
__device__ __forceinline__ float fast_sigmoid(float x) {
    return __fdividef(1.0f, 1.0f + __expf(-x));
}
__device__ __forceinline__ float fast_tanh(float x) {
    return 1.0f - __fdividef(2.0f, __expf(2.0f * x) + 1.0f);
}

// ---------------- init: zero h0 ---------------------------------------------
__global__ void init_state() {
    int i = blockIdx.x * blockDim.x + threadIdx.x;
    if (i < BATCH * HID) g_h[0][i] = __float2half(0.0f);
}

// ---------------- fp32 -> fp16 pre-conversion (once per run) ----------------
__global__ void conv_emb(const float* __restrict__ src) {
    const size_t i = (size_t)blockIdx.x * blockDim.x + threadIdx.x;
    if (i < (size_t)VOCAB * EMB / 8) {
        const float4 a = ((const float4*)src)[2 * i];
        const float4 b = ((const float4*)src)[2 * i + 1];
        uint4 o;
        o.x = pack_h2(a.x, a.y); o.y = pack_h2(a.z, a.w);
        o.z = pack_h2(b.x, b.y); o.w = pack_h2(b.z, b.w);
        ((uint4*)g_emb_h)[i] = o;
    }
}

__global__ void conv_wih(const float* __restrict__ src) {
    const size_t i = (size_t)blockIdx.x * blockDim.x + threadIdx.x;
    if (i < (size_t)GATES * EMB / 8) {
        const float4 a = ((const float4*)src)[2 * i];
        const float4 b = ((const float4*)src)[2 * i + 1];
        uint4 o;
        o.x = pack_h2(a.x, a.y); o.y = pack_h2(a.z, a.w);
        o.z = pack_h2(b.x, b.y); o.w = pack_h2(b.z, b.w);
        ((uint4*)g_wih_h)[i] = o;
    }
}

// ---------------- input projection: 3-stage cp.async, ldmatrix, fp16 out ----
// 128x128 tile, K-chunk 32 halfs, 16 chunks. ONE sync per chunk; fills issued
// two chunks ahead (fill(c+2) overwrites buf (c-1)%3, safe past iter-c sync).
__global__ void __launch_bounds__(256)
input_gemm(const int* __restrict__ x_seq, const float* __restrict__ b_ih,
           const float* __restrict__ b_hh) {
    extern __shared__ __align__(16) uint32_t igs[];   // [3][A|B tiles]
    __shared__ int stok[128];

    const int tid = threadIdx.x;
    const int bm = blockIdx.y;
    const int bn = blockIdx.x;

    if (tid < 128) stok[tid] = x_seq[bm * 128 + tid];
    __syncthreads();

    const int lane = tid & 31;
    const int w    = tid >> 5;
    const int wm   = w & 3;
    const int wn   = w >> 2;
    const int grp  = lane >> 2;
    const int q4   = lane & 3;

    uint32_t* sA = igs;                    // 3 x IG_TILE_W
    uint32_t* sB = igs + 3 * IG_TILE_W;    // 3 x IG_TILE_W

    float acc[2][8][4];
    #pragma unroll
    for (int i = 0; i < 2; i++)
        #pragma unroll
        for (int j = 0; j < 8; j++)
            #pragma unroll
            for (int r = 0; r < 4; r++) acc[i][j][r] = 0.0f;

    // cp.async fill: 128 rows x 4 segs (16B) per tile; 2 items/thread/tile
    const int frow0 = tid >> 2, fseg0 = tid & 3;
    const int frow1 = (tid + 256) >> 2, fseg1 = (tid + 256) & 3;
    auto fill = [&](int c) {
        const int buf = c % 3;
        const int kb = c * 32;
        uint32_t* A = sA + buf * IG_TILE_W;
        uint32_t* B = sB + buf * IG_TILE_W;
        cp_async16(smem_u32(A + frow0 * IG_STRIDE + fseg0 * 4),
                   g_emb_h + (size_t)stok[frow0] * EMB + kb + fseg0 * 8);
        cp_async16(smem_u32(A + frow1 * IG_STRIDE + fseg1 * 4),
                   g_emb_h + (size_t)stok[frow1] * EMB + kb + fseg1 * 8);
        cp_async16(smem_u32(B + frow0 * IG_STRIDE + fseg0 * 4),
                   g_wih_h + (size_t)(bn * 128 + frow0) * EMB + kb + fseg0 * 8);
        cp_async16(smem_u32(B + frow1 * IG_STRIDE + fseg1 * 4),
                   g_wih_h + (size_t)(bn * 128 + frow1) * EMB + kb + fseg1 * 8);
        cp_commit();
    };

    // ldmatrix lane bases (per buffer)
    uint32_t aL[3], bL[3];
    #pragma unroll
    for (int buf = 0; buf < 3; buf++) {
        aL[buf] = smem_u32(sA + buf * IG_TILE_W) +
            ((uint32_t)((wm * 32 + (lane & 15)) * IG_STRIDE) + ((lane >> 4) << 2)) * 4;
        bL[buf] = smem_u32(sB + buf * IG_TILE_W) +
            ((uint32_t)((wn * 64 + (lane & 15)) * IG_STRIDE) + ((lane >> 4) << 2)) * 4;
    }
    const uint32_t ROW16 = 16 * IG_STRIDE * 4;

    fill(0);
    fill(1);
    for (int c = 0; c < 16; c++) {
        if (c < 15) cp_wait1(); else cp_wait0();
        __syncthreads();
        if (c + 2 < 16) fill(c + 2);

        const int buf = c % 3;
        #pragma unroll
        for (int ks = 0; ks < 2; ks++) {
            const uint32_t kB = (uint32_t)ks * 32;
            uint32_t a0[4], a1[4];
            ldsm_x4(a0[0], a0[1], a0[2], a0[3], aL[buf] + kB);
            ldsm_x4(a1[0], a1[1], a1[2], a1[3], aL[buf] + ROW16 + kB);
            #pragma unroll
            for (int pair = 0; pair < 4; pair++) {
                uint32_t w0, w1, w2, w3;
                ldsm_x4(w0, w1, w2, w3, bL[buf] + (uint32_t)pair * ROW16 + kB);
                mma_f16(acc[0][pair * 2],     a0, w0, w2);
                mma_f16(acc[0][pair * 2 + 1], a0, w1, w3);
                mma_f16(acc[1][pair * 2],     a1, w0, w2);
                mma_f16(acc[1][pair * 2 + 1], a1, w1, w3);
            }
        }
    }

    // epilogue: + (b_ih + b_hh), write fp16 (paired __half2 stores)
    #pragma unroll
    for (int fm = 0; fm < 2; fm++)
        #pragma unroll
        for (int fn = 0; fn < 8; fn++) {
            const int row = bm * 128 + wm * 32 + fm * 16 + grp;
            const int col = bn * 128 + wn * 64 + fn * 8 + q4 * 2;
            const float bi0 = b_ih[col] + b_hh[col];
            const float bi1 = b_ih[col + 1] + b_hh[col + 1];
            *(uint32_t*)(g_xgates + (size_t)row * GATES + col) =
                pack_h2(acc[fm][fn][0] + bi0, acc[fm][fn][1] + bi1);
            *(uint32_t*)(g_xgates + (size_t)(row + 8) * GATES + col) =
                pack_h2(acc[fm][fn][2] + bi0, acc[fm][fn][3] + bi1);
        }
}

// ---------------- persistent recurrence (R10; xg prefetch now fp16) ---------
__global__ void __launch_bounds__(NTHREADS, 1)
lstm_persistent(const float* __restrict__ W_hh, float* __restrict__ out) {
    extern __shared__ char smem[];
    const uint32_t smb = smem_u32(smem);
    uint32_t* sW   = (uint32_t*)(smem + SMO_W);
    float*    gbuf = (float*)(smem + SMO_GBUF);   // [2][64][33]

    const int tid  = threadIdx.x;
    const int hj   = blockIdx.x * 8;
    const int lane = tid & 31;
    const int w    = tid >> 5;
    const int wm   = w & 3;          // m base wm*16
    const int kh   = w >> 2;         // K-half: even(0)/odd(1) k-steps
    const int grp  = lane >> 2;
    const int q4   = lane & 3;

    // ---- one-time: W slice (32 x 1024) -> smem fp16 ----
    for (int it = tid; it < 32 * 512; it += NTHREADS) {
        const int n  = it >> 9;
        const int w2 = it & 511;
        const float2 v = *(const float2*)(
            W_hh + (size_t)((n >> 3) * HID + hj + (n & 7)) * HID + w2 * 2);
        sW[n * SW_STRIDE + w2] = pack_h2(v.x, v.y);
    }
    __syncthreads();

    // ldmatrix lane base addresses (bytes)
    const uint32_t aAddrL = smb + SMO_A +
        ((uint32_t)(wm * 16 + (lane & 15)) * SA_STRIDE + ((lane >> 4) << 2)) * 4;
    const uint32_t wAddr0 = smb + SMO_W +
        ((uint32_t)(lane & 15) * SW_STRIDE + ((lane >> 4) << 2)) * 4;
    const uint32_t wAddr1 = wAddr0 + 16 * SW_STRIDE * 4;

    auto fill = [&](const __half* h_in, int c) {
        const int buf = c % 3;
        #pragma unroll
        for (int j = 0; j < 8; j++) {
            const int gi = tid + j * NTHREADS;
            const int b  = gi >> 5;
            const int g  = gi & 31;
            cp_async16(smb + SMO_A + (buf * SA_BUF_W + b * SA_STRIDE + g * 4) * 4,
                       h_in + (size_t)b * HID + c * 256 + g * 8);
        }
        cp_commit();
    };

    // epilogue item indices (fixed per thread)
    const int eb0 = tid >> 3,               ehh0 = tid & 7;
    const int eb1 = (tid + NTHREADS) >> 3,  ehh1 = (tid + NTHREADS) & 7;

    float creg[2] = {0.f, 0.f};            // cell state lives in registers

    for (int t = 0; t < T_SEQ; t++) {
        const __half* __restrict__ h_in  = g_h[t & 1];
        __half* __restrict__       h_out = g_h[(t + 1) & 1];

        float acc[4][4];
        #pragma unroll
        for (int i = 0; i < 4; i++)
            #pragma unroll
            for (int r = 0; r < 4; r++) acc[i][r] = 0.0f;

        fill(h_in, 0);

        // prefetch xgates (fp16) for this step's epilogue
        float xg0[4], xg1[4];
        {
            const __half* p0 = g_xgates + ((size_t)t * BATCH + eb0) * GATES + hj + ehh0;
            const __half* p1 = g_xgates + ((size_t)t * BATCH + eb1) * GATES + hj + ehh1;
            #pragma unroll
            for (int g = 0; g < 4; g++) {
                xg0[g] = __half2float(__ldg(p0 + g * HID));
                xg1[g] = __half2float(__ldg(p1 + g * HID));
            }
        }

        #pragma unroll
        for (int c = 0; c < 4; c++) {
            if (c < 3) { fill(h_in, c + 1); cp_wait1(); }
            else       { cp_wait0(); }
            __syncthreads();

            const uint32_t aBase = aAddrL + (uint32_t)(c % 3) * (SA_BUF_W * 4);
            const uint32_t wOff  = (uint32_t)(c * 16) * 32;   // kw bytes
            #pragma unroll
            for (int ksl2 = 0; ksl2 < 8; ksl2++) {
                const int ksl = ksl2 * 2 + kh;       // interleaved K split
                uint32_t af[4];
                ldsm_x4(af[0], af[1], af[2], af[3], aBase + (uint32_t)ksl * 32);
                uint32_t w00, w01, w02, w03;
                ldsm_x4(w00, w01, w02, w03, wAddr0 + wOff + (uint32_t)ksl * 32);
                mma_f16(acc[0], af, w00, w02);
                mma_f16(acc[1], af, w01, w03);
                uint32_t w10, w11, w12, w13;
                ldsm_x4(w10, w11, w12, w13, wAddr1 + wOff + (uint32_t)ksl * 32);
                mma_f16(acc[2], af, w10, w12);
                mma_f16(acc[3], af, w11, w13);
            }
        }

        // park partial accumulators (per K-half)
        {
            float* gb = gbuf + kh * GBUF_W;
            const int row = wm * 16 + grp;
            #pragma unroll
            for (int fn = 0; fn < 4; fn++) {
                const int col = fn * 8 + q4 * 2;
                gb[row * 33 + col]           = acc[fn][0];
                gb[row * 33 + col + 1]       = acc[fn][1];
                gb[(row + 8) * 33 + col]     = acc[fn][2];
                gb[(row + 8) * 33 + col + 1] = acc[fn][3];
            }
        }
        __syncthreads();

        // fused elementwise: sum the two K-half partials + xg
        float hnew[2];
        #pragma unroll
        for (int it2 = 0; it2 < 2; it2++) {
            const int b    = it2 ? eb1 : eb0;
            const int hh   = it2 ? ehh1 : ehh0;
            const float* xg = it2 ? xg1 : xg0;
            const int hcol = hj + hh;

            const float ip = gbuf[b * 33 + hh]      + gbuf[GBUF_W + b * 33 + hh]      + xg[0];
            const float fp = gbuf[b * 33 + 8 + hh]  + gbuf[GBUF_W + b * 33 + 8 + hh]  + xg[1];
            const float gp = gbuf[b * 33 + 16 + hh] + gbuf[GBUF_W + b * 33 + 16 + hh] + xg[2];
            const float op = gbuf[b * 33 + 24 + hh] + gbuf[GBUF_W + b * 33 + 24 + hh] + xg[3];

            const float ig = fast_sigmoid(ip);
            const float fg = fast_sigmoid(fp);
            const float gg = fast_tanh(gp);
            const float og = fast_sigmoid(op);

            const float c_new = fg * creg[it2] + ig * gg;
            const float h_new = og * fast_tanh(c_new);
            creg[it2] = c_new;
            hnew[it2] = h_new;

            h_out[b * HID + hcol] = __float2half_rn(h_new);
        }

        // ---- grid barrier: single atomic, release early, overlap stores ----
        __syncthreads();                    // all h_out stores done
        unsigned target = 0;
        if (tid == 0) {
            __threadfence();
            unsigned old;
            asm volatile("atom.add.release.gpu.global.u32 %0, [%1], 1;"
                         : "=r"(old) : "l"(&g_bar) : "memory");
            target = old - (old % NCTA) + NCTA;
        }
        // fp32 output stores overlap the barrier poll below
        out[((size_t)t * BATCH + eb0) * HID + hj + ehh0] = hnew[0];
        out[((size_t)t * BATCH + eb1) * HID + hj + ehh1] = hnew[1];
        if (tid == 0) {
            unsigned cur;
            do {
                asm volatile("ld.acquire.gpu.global.u32 %0, [%1];"
                             : "=r"(cur) : "l"(&g_bar) : "memory");
            } while ((int)(cur - target) < 0);
        }
        __syncthreads();
    }

    // final cell state -> global (finalize reads it)
    g_c[eb0 * HID + hj + ehh0] = creg[0];
    g_c[eb1 * HID + hj + ehh1] = creg[1];
}

// ---------------- finalize: append (h, c) after outs ------------------------
__global__ void finalize(float* __restrict__ out) {
    int i = blockIdx.x * blockDim.x + threadIdx.x;
    if (i < BATCH * HID) {
        out[(size_t)T_SEQ * BATCH * HID + i] =
            out[(size_t)(T_SEQ - 1) * BATCH * HID + i];
        out[(size_t)T_SEQ * BATCH * HID + BATCH * HID + i] = g_c[i];
    }
}

// ---------------- launch -----------------------------------------------------
extern "C" void kernel_launch(void* const* d_in, const int* in_sizes, int n_in,
                              void* d_out, int out_size) {
    const int*   x_seq = (const int*)d_in[0];
    const float* emb   = (const float*)d_in[1];
    const float* W_ih  = (const float*)d_in[2];
    const float* W_hh  = (const float*)d_in[3];
    const float* b_ih  = (const float*)d_in[4];
    const float* b_hh  = (const float*)d_in[5];
    float* out = (float*)d_out;

    cudaFuncSetAttribute(lstm_persistent,
                         cudaFuncAttributeMaxDynamicSharedMemorySize, SMEM_BYTES);
    cudaFuncSetAttribute(input_gemm,
                         cudaFuncAttributeMaxDynamicSharedMemorySize, IG_SMEM_BYTES);

    init_state<<<(BATCH * HID + 255) / 256, 256>>>();

    conv_emb<<<(int)(((size_t)VOCAB * EMB / 8 + 255) / 256), 256>>>(emb);
    conv_wih<<<(int)(((size_t)GATES * EMB / 8 + 255) / 256), 256>>>(W_ih);

    dim3 ig_grid(GATES / 128, (T_SEQ * BATCH) / 128);   // (32, 128)
    input_gemm<<<ig_grid, 256, IG_SMEM_BYTES>>>(x_seq, b_ih, b_hh);

    lstm_persistent<<<NCTA, NTHREADS, SMEM_BYTES>>>(W_hh, out);

    finalize<<<(BATCH * HID + 255) / 256, 256>>>(out);
}